// round 3
// baseline (speedup 1.0000x reference)
#include <cuda_runtime.h>
#include <cstdint>

typedef unsigned long long ull;

#define NH 4
#define HD 32
#define PX 68    // Xst / Ot pitch (floats)
#define PW 132   // staged weight pitch
#define PQ 132   // Q/K/V/Y pitch
#define SC_Q 0.17677669529663687f  // 32^-0.5

// packed fp32x2 FMA (sm_10x): doubles fp32 throughput vs FFMA
__device__ __forceinline__ void fma2(ull &d, ull a, ull b) {
    asm volatile("fma.rn.f32x2 %0, %1, %2, %0;" : "+l"(d) : "l"(a), "l"(b));
}
__device__ __forceinline__ ull pack2(float x) {
    ull d; unsigned u = __float_as_uint(x);
    asm volatile("mov.b64 %0, {%1, %1};" : "=l"(d) : "r"(u));
    return d;
}
__device__ __forceinline__ float2 unpack2(ull d) {
    float2 r;
    asm volatile("mov.b64 {%0, %1}, %2;" : "=f"(r.x), "=f"(r.y) : "l"(d));
    return r;
}

// smem layout (floats): Xst[128*PX] | Ws[128*PW] | Qs[64*PQ] | Ks | Vs | Bt[900]
#define SMEM_FLOATS (128*PX + 128*PW + 3*64*PQ + 900)

__global__ void __launch_bounds__(256, 1)
wattn_kernel(const float* __restrict__ x, const float* __restrict__ qkv_w,
             const float* __restrict__ qkv_b, const float* __restrict__ proj_w,
             const float* __restrict__ proj_b, const float* __restrict__ rpb,
             float* __restrict__ out)
{
    extern __shared__ float sm[];
    float* Xst = sm;                 // [128][PX]  input (k-major), later attn output (k-major)
    float* Ws  = Xst + 128*PX;       // [128][PW]  staged weights, Ws[k][j]
    float* Qs  = Ws  + 128*PW;       // [64][PQ]   Q (prescaled), later final Y
    float* Ks  = Qs  + 64*PQ;
    float* Vs  = Ks  + 64*PQ;
    float* Bt  = Vs  + 64*PQ;        // rpb table [225*4]

    const int tid = threadIdx.x;
    int wid = blockIdx.x;
    const int wn = wid & 7;  wid >>= 3;
    const int hn = wid & 7;  wid >>= 3;
    const int v  = wid % 5;  wid /= 5;
    const int u  = wid % 5;
    const int b  = wid / 5;

    // base for (b, c=0, u, v): layout (B,C,U,V,H,W), C-stride = 25*4096 = 102400
    const int base = (((b << 7) * 5 + u) * 5 + v) * 4096;
    const float* xb = x + base;

    // ---- Phase 1: roll + window gather into Xst[c][s] ----
    #pragma unroll
    for (int i = tid; i < 8192; i += 256) {
        int c = i >> 6, s = i & 63;
        int sh = ((hn << 3) + (s >> 3) - 4) & 63;
        int sw = ((wn << 3) + (s & 7) - 4) & 63;
        Xst[c * PX + s] = __ldg(xb + c * 102400 + sh * 64 + sw);
    }
    for (int i = tid; i < 900; i += 256) Bt[i] = rpb[i];
    __syncthreads();

    // weight stager: Ws[k][j] = gw[j*128 + k]   (all 256 threads)
    auto stageW = [&](const float* gw) {
        int j  = tid >> 1;
        int k0 = (tid & 1) << 6;
        const float4* src = reinterpret_cast<const float4*>(gw + j * 128 + k0);
        #pragma unroll
        for (int i = 0; i < 16; i++) {
            float4 w4 = src[i];
            int k = k0 + (i << 2);
            Ws[(k + 0) * PW + j] = w4.x;
            Ws[(k + 1) * PW + j] = w4.y;
            Ws[(k + 2) * PW + j] = w4.z;
            Ws[(k + 3) * PW + j] = w4.w;
        }
    };

    // GEMM core: 128 threads, 8 rows x 8 cols per thread (cols split ct*4 and 64+ct*4
    // for conflict-free LDS.128). Result: acc[8][4] of f32x2 pairs.
    const int rt = tid >> 4;   // 0..7 (valid when tid < 128)
    const int ct = tid & 15;   // 0..15

    auto gemm_core = [&](const float* A, int pa, ull acc[8][4]) {
        #pragma unroll
        for (int r = 0; r < 8; r++)
            #pragma unroll
            for (int p = 0; p < 4; p++) acc[r][p] = 0ULL;
        #pragma unroll 4
        for (int k = 0; k < 128; k++) {
            const float* Ar = A + k * pa + rt * 8;
            float4 a0 = *(const float4*)(Ar);
            float4 a1 = *(const float4*)(Ar + 4);
            const ulonglong2* Br = (const ulonglong2*)(Ws + k * PW);
            ulonglong2 bA = Br[ct];        // cols ct*4 .. ct*4+3
            ulonglong2 bB = Br[16 + ct];   // cols 64+ct*4 ..
            float ar[8] = {a0.x, a0.y, a0.z, a0.w, a1.x, a1.y, a1.z, a1.w};
            #pragma unroll
            for (int r = 0; r < 8; r++) {
                ull ap = pack2(ar[r]);
                fma2(acc[r][0], ap, bA.x);
                fma2(acc[r][1], ap, bA.y);
                fma2(acc[r][2], ap, bB.x);
                fma2(acc[r][3], ap, bB.y);
            }
        }
    };

    // ---- Phase 2: QKV = Xw @ qkv_w^T + b, interleaved-head layout ----
    // global channel j in [0,384): h=j/96, r=j%96, seg=r/32 (0=q,1=k,2=v), col=h*32+(r%32)
    #pragma unroll 1
    for (int p = 0; p < 3; p++) {
        stageW(qkv_w + p * 16384);
        __syncthreads();
        if (tid < 128) {
            ull acc[8][4];
            gemm_core(Xst, PX, acc);
            #pragma unroll
            for (int g = 0; g < 2; g++) {
                int j   = p * 128 + g * 64 + ct * 4;
                int hh  = j / 96;
                int r   = j - hh * 96;
                int seg = r >> 5;
                int col = hh * 32 + (r & 31);
                float* dst = (seg == 0) ? Qs : (seg == 1) ? Ks : Vs;
                float sc   = (seg == 0) ? SC_Q : 1.0f;
                float4 b4  = *(const float4*)(qkv_b + j);
                #pragma unroll
                for (int r8 = 0; r8 < 8; r8++) {
                    int s = rt * 8 + r8;
                    float2 p0 = unpack2(acc[r8][g * 2 + 0]);
                    float2 p1 = unpack2(acc[r8][g * 2 + 1]);
                    float4 o;
                    o.x = (p0.x + b4.x) * sc;
                    o.y = (p0.y + b4.y) * sc;
                    o.z = (p1.x + b4.z) * sc;
                    o.w = (p1.y + b4.w) * sc;
                    *(float4*)(dst + s * PQ + col) = o;
                }
            }
        }
        __syncthreads();
    }

    // stage proj weights now (Ws free; overlaps ahead of attention)
    stageW(proj_w);

    // ---- Phase 3: attention. thread = (head h, query q). exact softmax. ----
    {
        const int h = tid >> 6;
        const int q = tid & 63;
        ull qp[16];
        const ull* qrow = (const ull*)(Qs + q * PQ + h * HD);
        #pragma unroll
        for (int d = 0; d < 16; d++) qp[d] = qrow[d];

        float lg[64];
        const int qi = q >> 3, qj = q & 7;
        #pragma unroll
        for (int t = 0; t < 64; t++) {
            const ull* kr = (const ull*)(Ks + t * PQ + h * HD);
            ull a = 0ULL;
            #pragma unroll
            for (int d = 0; d < 16; d++) fma2(a, qp[d], kr[d]);
            float2 s2 = unpack2(a);
            int ridx = (qi - (t >> 3) + 7) * 15 + (qj - (t & 7) + 7);
            lg[t] = s2.x + s2.y + Bt[ridx * 4 + h];
        }
        float m = lg[0];
        #pragma unroll
        for (int t = 1; t < 64; t++) m = fmaxf(m, lg[t]);
        float l = 0.f;
        #pragma unroll
        for (int t = 0; t < 64; t++) { float e = __expf(lg[t] - m); lg[t] = e; l += e; }
        float inv = __fdividef(1.0f, l);

        ull op[16];
        #pragma unroll
        for (int d = 0; d < 16; d++) op[d] = 0ULL;
        #pragma unroll
        for (int t = 0; t < 64; t++) {
            ull pp = pack2(lg[t]);
            const ull* vr = (const ull*)(Vs + t * PQ + h * HD);
            #pragma unroll
            for (int d = 0; d < 16; d++) fma2(op[d], pp, vr[d]);
        }
        // write attention output transposed (k-major) into Xst for proj GEMM
        #pragma unroll
        for (int d = 0; d < 16; d++) {
            float2 o2 = unpack2(op[d]);
            int c = h * HD + 2 * d;
            Xst[c * PX + q]       = o2.x * inv;
            Xst[(c + 1) * PX + q] = o2.y * inv;
        }
    }
    __syncthreads();

    // ---- Phase 4: proj GEMM -> Y into Qs buffer ----
    if (tid < 128) {
        ull acc[8][4];
        gemm_core(Xst, PX, acc);
        #pragma unroll
        for (int g = 0; g < 2; g++) {
            int j = g * 64 + ct * 4;
            float4 b4 = *(const float4*)(proj_b + j);
            #pragma unroll
            for (int r8 = 0; r8 < 8; r8++) {
                int s = rt * 8 + r8;
                float2 p0 = unpack2(acc[r8][g * 2 + 0]);
                float2 p1 = unpack2(acc[r8][g * 2 + 1]);
                float4 o;
                o.x = p0.x + b4.x;
                o.y = p0.y + b4.y;
                o.z = p1.x + b4.z;
                o.w = p1.y + b4.w;
                *(float4*)(Qs + s * PQ + j) = o;
            }
        }
    }
    __syncthreads();

    // ---- Phase 5: coalesced reverse-roll scatter ----
    float* ob = out + base;
    #pragma unroll
    for (int i = tid; i < 8192; i += 256) {
        int c = i >> 6, s = i & 63;
        int sh = ((hn << 3) + (s >> 3) - 4) & 63;
        int sw = ((wn << 3) + (s & 7) - 4) & 63;
        ob[c * 102400 + sh * 64 + sw] = Qs[s * PQ + c];
    }
}

extern "C" void kernel_launch(void* const* d_in, const int* in_sizes, int n_in,
                              void* d_out, int out_size) {
    (void)in_sizes; (void)n_in; (void)out_size;
    size_t smem = SMEM_FLOATS * sizeof(float);
    cudaFuncSetAttribute(wattn_kernel, cudaFuncAttributeMaxDynamicSharedMemorySize, (int)smem);
    wattn_kernel<<<3200, 256, smem>>>(
        (const float*)d_in[0], (const float*)d_in[1], (const float*)d_in[2],
        (const float*)d_in[3], (const float*)d_in[4], (const float*)d_in[5],
        (float*)d_out);
}

// round 4
// speedup vs baseline: 1.0547x; 1.0547x over previous
#include <cuda_runtime.h>
#include <cstdint>

typedef unsigned long long ull;

#define PX 68    // Xst pitch (floats)
#define PW 132   // staged weight chunk pitch
#define PQ 132   // Q/K/V/Y pitch
#define SC_Q 0.17677669529663687f  // 32^-0.5

// packed fp32x2 FMA (sm_10x): doubles fp32 throughput vs FFMA
__device__ __forceinline__ void fma2(ull &d, ull a, ull b) {
    asm volatile("fma.rn.f32x2 %0, %1, %2, %0;" : "+l"(d) : "l"(a), "l"(b));
}
__device__ __forceinline__ ull pack2(float x) {
    ull d; unsigned u = __float_as_uint(x);
    asm volatile("mov.b64 %0, {%1, %1};" : "=l"(d) : "r"(u));
    return d;
}
__device__ __forceinline__ float2 unpack2(ull d) {
    float2 r;
    asm volatile("mov.b64 {%0, %1}, %2;" : "=f"(r.x), "=f"(r.y) : "l"(d));
    return r;
}

// smem (floats): Xst[128*PX] | Wb0[64*PW] | Wb1[64*PW] | Qs | Ks | Vs | Bt[900]
#define SMEM_FLOATS (128*PX + 2*64*PW + 3*64*PQ + 900)

__global__ void __launch_bounds__(256, 1)
wattn_kernel(const float* __restrict__ x, const float* __restrict__ qkv_w,
             const float* __restrict__ qkv_b, const float* __restrict__ proj_w,
             const float* __restrict__ proj_b, const float* __restrict__ rpb,
             float* __restrict__ out)
{
    extern __shared__ float sm[];
    float* Xst = sm;                  // [128][PX] input (k-major), later attn out (k-major)
    float* Wb0 = Xst + 128 * PX;      // [64][PW] weight chunk buffer 0
    float* Wb1 = Wb0 + 64 * PW;       // [64][PW] weight chunk buffer 1
    float* Qs  = Wb1 + 64 * PW;       // [64][PQ] Q (prescaled), later final Y
    float* Ks  = Qs + 64 * PQ;
    float* Vs  = Ks + 64 * PQ;
    float* Bt  = Vs + 64 * PQ;        // rpb [225*4]

    const int tid = threadIdx.x;
    int wid = blockIdx.x;
    const int wn = wid & 7;  wid >>= 3;
    const int hn = wid & 7;  wid >>= 3;
    const int v  = wid % 5;  wid /= 5;
    const int u  = wid % 5;
    const int b  = wid / 5;

    // base for (b, c=0, u, v): layout (B,C,U,V,H,W), C-stride = 25*4096 = 102400
    const int base = (((b << 7) * 5 + u) * 5 + v) * 4096;
    const float* xb = x + base;

    // ---- weight staging coords: thread stages col sj, k-offset skk..skk+31 of a chunk ----
    const int sj  = tid >> 1;
    const int skk = (tid & 1) << 5;

    // chunk c (0..7): pass p=c>>1 (0..2 qkv, 3 proj), half=(c&1) selects k range 0..63 / 64..127
    float4 wp[8];
    auto prefetchW = [&](int c) {
        int p = c >> 1;
        const float* basew = (p < 3) ? (qkv_w + p * 16384) : proj_w;
        const float4* s4 = (const float4*)(basew + sj * 128 + ((c & 1) << 6) + skk);
        #pragma unroll
        for (int i = 0; i < 8; i++) wp[i] = s4[i];
    };
    auto stsW = [&](float* Wb) {
        #pragma unroll
        for (int i = 0; i < 8; i++) {
            int kk = skk + (i << 2);
            Wb[(kk + 0) * PW + sj] = wp[i].x;
            Wb[(kk + 1) * PW + sj] = wp[i].y;
            Wb[(kk + 2) * PW + sj] = wp[i].z;
            Wb[(kk + 3) * PW + sj] = wp[i].w;
        }
    };

    // ---- Phase 1: prefetch chunk0, roll+window gather, rpb, stage chunk0 ----
    prefetchW(0);
    #pragma unroll
    for (int i = tid; i < 8192; i += 256) {
        int c = i >> 6, s = i & 63;
        int sh = ((hn << 3) + (s >> 3) - 4) & 63;
        int sw = ((wn << 3) + (s & 7) - 4) & 63;
        Xst[c * PX + s] = __ldg(xb + c * 102400 + sh * 64 + sw);
    }
    for (int i = tid; i < 900; i += 256) Bt[i] = rpb[i];
    stsW(Wb0);
    __syncthreads();

    // ---- GEMM: 256 threads, 8 rows x 4 cols each ----
    const int rt = tid >> 5;   // row block (rows rt*8..rt*8+7) — constant per warp (A broadcast)
    const int ct = tid & 31;   // col group (cols ct*4..ct*4+3)

    ull acc[8][2];
    auto gemm_chunk = [&](const float* Wb, int kbase) {
        #pragma unroll 8
        for (int kk = 0; kk < 64; kk++) {
            const float* Ar = Xst + (kbase + kk) * PX + (rt << 3);
            float4 a0 = *(const float4*)(Ar);
            float4 a1 = *(const float4*)(Ar + 4);
            ulonglong2 bb = *(const ulonglong2*)(Wb + kk * PW + (ct << 2));
            float ar[8] = {a0.x, a0.y, a0.z, a0.w, a1.x, a1.y, a1.z, a1.w};
            #pragma unroll
            for (int r = 0; r < 8; r++) {
                ull ap = pack2(ar[r]);
                fma2(acc[r][0], ap, bb.x);
                fma2(acc[r][1], ap, bb.y);
            }
        }
    };

    // ---- Phase 2: QKV passes, double-buffered k-chunks, staging overlapped ----
    #pragma unroll 1
    for (int c = 0; c < 6; c++) {
        if ((c & 1) == 0) {
            #pragma unroll
            for (int r = 0; r < 8; r++) { acc[r][0] = 0ULL; acc[r][1] = 0ULL; }
        }
        prefetchW(c + 1);                        // next chunk -> regs (latency hidden by gemm)
        gemm_chunk((c & 1) ? Wb1 : Wb0, (c & 1) << 6);
        stsW((c & 1) ? Wb0 : Wb1);               // chunk c+1 -> other buffer
        if (c & 1) {
            // epilogue for qkv pass p: remap interleaved-head channels to Q/K/V
            int p = c >> 1;
            int j = p * 128 + (ct << 2);
            int hh = j / 96;
            int r  = j - hh * 96;
            int seg = r >> 5;
            int col = (hh << 5) + (r & 31);
            float* dst = (seg == 0) ? Qs : (seg == 1) ? Ks : Vs;
            float sc   = (seg == 0) ? SC_Q : 1.0f;
            float4 b4 = *(const float4*)(qkv_b + j);
            #pragma unroll
            for (int r8 = 0; r8 < 8; r8++) {
                int s = (rt << 3) + r8;
                float2 p0 = unpack2(acc[r8][0]);
                float2 p1 = unpack2(acc[r8][1]);
                float4 o;
                o.x = (p0.x + b4.x) * sc;
                o.y = (p0.y + b4.y) * sc;
                o.z = (p1.x + b4.z) * sc;
                o.w = (p1.y + b4.w) * sc;
                *(float4*)(dst + s * PQ + col) = o;
            }
        }
        __syncthreads();
    }
    // buffers now: Wb0 = proj k[0:64) (chunk 6). Chunk 7 staged during attention.

    // ---- Phase 3: attention. thread = (head h, query q). exact softmax. ----
    {
        prefetchW(7);                            // proj k[64:128) -> regs, STS after attention
        const int h = tid >> 6;
        const int q = tid & 63;
        ulonglong2 qp[8];
        const ulonglong2* qr = (const ulonglong2*)(Qs + q * PQ + (h << 5));
        #pragma unroll
        for (int d = 0; d < 8; d++) qp[d] = qr[d];

        float lg[64];
        const int qi = q >> 3, qj = q & 7;
        #pragma unroll
        for (int t = 0; t < 64; t++) {
            const ulonglong2* kr = (const ulonglong2*)(Ks + t * PQ + (h << 5));
            ull a0 = 0ULL, a1 = 0ULL, a2 = 0ULL, a3 = 0ULL;
            #pragma unroll
            for (int d = 0; d < 8; d += 2) {
                ulonglong2 k0 = kr[d];
                ulonglong2 k1 = kr[d + 1];
                fma2(a0, qp[d].x, k0.x);
                fma2(a1, qp[d].y, k0.y);
                fma2(a2, qp[d + 1].x, k1.x);
                fma2(a3, qp[d + 1].y, k1.y);
            }
            float2 s0 = unpack2(a0), s1 = unpack2(a1), s2 = unpack2(a2), s3 = unpack2(a3);
            int ridx = (qi - (t >> 3) + 7) * 15 + (qj - (t & 7) + 7);
            lg[t] = ((s0.x + s0.y) + (s1.x + s1.y)) + ((s2.x + s2.y) + (s3.x + s3.y))
                    + Bt[ridx * 4 + h];
        }
        float m = lg[0];
        #pragma unroll
        for (int t = 1; t < 64; t++) m = fmaxf(m, lg[t]);
        float l = 0.f;
        #pragma unroll
        for (int t = 0; t < 64; t++) { float e = __expf(lg[t] - m); lg[t] = e; l += e; }
        float inv = __fdividef(1.0f, l);

        ull op[16];
        #pragma unroll
        for (int d = 0; d < 16; d++) op[d] = 0ULL;
        #pragma unroll
        for (int t = 0; t < 64; t++) {
            ull pp = pack2(lg[t]);
            const ulonglong2* vr = (const ulonglong2*)(Vs + t * PQ + (h << 5));
            #pragma unroll
            for (int d = 0; d < 8; d++) {
                fma2(op[2 * d],     pp, vr[d].x);
                fma2(op[2 * d + 1], pp, vr[d].y);
            }
        }
        // write attention output transposed (k-major) into Xst for proj GEMM
        #pragma unroll
        for (int d = 0; d < 16; d++) {
            float2 o2 = unpack2(op[d]);
            int c = (h << 5) + 2 * d;
            Xst[c * PX + q]       = o2.x * inv;
            Xst[(c + 1) * PX + q] = o2.y * inv;
        }
        stsW(Wb1);                               // proj k[64:128) -> Wb1
    }
    __syncthreads();

    // ---- Phase 4: proj GEMM -> Y into Qs buffer ----
    {
        #pragma unroll
        for (int r = 0; r < 8; r++) { acc[r][0] = 0ULL; acc[r][1] = 0ULL; }
        gemm_chunk(Wb0, 0);
        gemm_chunk(Wb1, 64);
        int j = ct << 2;
        float4 b4 = *(const float4*)(proj_b + j);
        #pragma unroll
        for (int r8 = 0; r8 < 8; r8++) {
            int s = (rt << 3) + r8;
            float2 p0 = unpack2(acc[r8][0]);
            float2 p1 = unpack2(acc[r8][1]);
            float4 o;
            o.x = p0.x + b4.x;
            o.y = p0.y + b4.y;
            o.z = p1.x + b4.z;
            o.w = p1.y + b4.w;
            *(float4*)(Qs + s * PQ + j) = o;
        }
    }
    __syncthreads();

    // ---- Phase 5: coalesced reverse-roll scatter ----
    float* ob = out + base;
    #pragma unroll
    for (int i = tid; i < 8192; i += 256) {
        int c = i >> 6, s = i & 63;
        int sh = ((hn << 3) + (s >> 3) - 4) & 63;
        int sw = ((wn << 3) + (s & 7) - 4) & 63;
        ob[c * 102400 + sh * 64 + sw] = Qs[s * PQ + c];
    }
}

extern "C" void kernel_launch(void* const* d_in, const int* in_sizes, int n_in,
                              void* d_out, int out_size) {
    (void)in_sizes; (void)n_in; (void)out_size;
    size_t smem = SMEM_FLOATS * sizeof(float);
    cudaFuncSetAttribute(wattn_kernel, cudaFuncAttributeMaxDynamicSharedMemorySize, (int)smem);
    wattn_kernel<<<3200, 256, smem>>>(
        (const float*)d_in[0], (const float*)d_in[1], (const float*)d_in[2],
        (const float*)d_in[3], (const float*)d_in[4], (const float*)d_in[5],
        (float*)d_out);
}

// round 5
// speedup vs baseline: 1.2513x; 1.1865x over previous
#include <cuda_runtime.h>
#include <cstdint>

typedef unsigned long long ull;

#define PX 68    // Xst pitch (floats)
#define PQ 132   // Q/K/V/Y pitch
#define SC_Q 0.17677669529663687f  // 32^-0.5

// packed fp32x2 FMA (sm_10x): doubles fp32 throughput vs FFMA
__device__ __forceinline__ void fma2(ull &d, ull a, ull b) {
    asm volatile("fma.rn.f32x2 %0, %1, %2, %0;" : "+l"(d) : "l"(a), "l"(b));
}
__device__ __forceinline__ ull pack2(float x) {
    ull d; unsigned u = __float_as_uint(x);
    asm volatile("mov.b64 %0, {%1, %1};" : "=l"(d) : "r"(u));
    return d;
}
__device__ __forceinline__ float2 unpack2(ull d) {
    float2 r;
    asm volatile("mov.b64 {%0, %1}, %2;" : "=f"(r.x), "=f"(r.y) : "l"(d));
    return r;
}

// Pre-transposed weights: Wt[k][j], j in [0,384) = qkv row j, j in [384,512) = proj row j-384
__device__ float Wt_g[128 * 512];

__global__ void __launch_bounds__(256)
prep_w_kernel(const float* __restrict__ qkv_w, const float* __restrict__ proj_w) {
    int i = blockIdx.x * 256 + threadIdx.x;   // 65536 total
    int k = i >> 9, j = i & 511;
    Wt_g[i] = (j < 384) ? qkv_w[j * 128 + k] : proj_w[(j - 384) * 128 + k];
}

// smem (floats): Xst[128*PX] | Qs[64*PQ] | Ks | Vs | Bt[900]   (~140 KB)
#define SMEM_FLOATS (128*PX + 3*64*PQ + 900)

__global__ void __launch_bounds__(256, 1)
wattn_kernel(const float* __restrict__ x, const float* __restrict__ qkv_b,
             const float* __restrict__ proj_b, const float* __restrict__ rpb,
             float* __restrict__ out)
{
    extern __shared__ float sm[];
    float* Xst = sm;                  // [128][PX] input (k-major), later attn out (k-major)
    float* Qs  = Xst + 128 * PX;      // [64][PQ] Q (prescaled), later final Y
    float* Ks  = Qs + 64 * PQ;
    float* Vs  = Ks + 64 * PQ;
    float* Bt  = Vs + 64 * PQ;        // rpb [225*4]

    const int tid = threadIdx.x;
    int wid = blockIdx.x;
    const int wn = wid & 7;  wid >>= 3;
    const int hn = wid & 7;  wid >>= 3;
    const int v  = wid % 5;  wid /= 5;
    const int u  = wid % 5;
    const int b  = wid / 5;

    // base for (b, c=0, u, v): layout (B,C,U,V,H,W), C-stride = 25*4096 = 102400
    const int base = (((b << 7) * 5 + u) * 5 + v) * 4096;
    const float* xb = x + base;

    // ---- Phase 1: roll + window gather into Xst[c][s]; rpb -> Bt ----
    #pragma unroll
    for (int i = tid; i < 8192; i += 256) {
        int c = i >> 6, s = i & 63;
        int sh = ((hn << 3) + (s >> 3) - 4) & 63;
        int sw = ((wn << 3) + (s & 7) - 4) & 63;
        Xst[c * PX + s] = __ldg(xb + c * 102400 + sh * 64 + sw);
    }
    for (int i = tid; i < 900; i += 256) Bt[i] = rpb[i];
    __syncthreads();

    // ---- GEMM: 256 threads, 8 rows x 4 cols each. B direct from global Wt. ----
    const int rt = tid >> 5;   // row block (rows rt*8..+7) — constant per warp (A broadcast)
    const int ct = tid & 31;   // col group (cols ct*4..+3)

    ull acc[8][2];
    auto gemm_pass = [&](int joff) {
        #pragma unroll
        for (int r = 0; r < 8; r++) { acc[r][0] = 0ULL; acc[r][1] = 0ULL; }
        const float* Bp = Wt_g + joff + (ct << 2);
        #pragma unroll 8
        for (int k = 0; k < 128; k++) {
            const float* Ar = Xst + k * PX + (rt << 3);
            float4 a0 = *(const float4*)(Ar);
            float4 a1 = *(const float4*)(Ar + 4);
            ulonglong2 bb = *(const ulonglong2*)(Bp + (k << 9));
            float ar[8] = {a0.x, a0.y, a0.z, a0.w, a1.x, a1.y, a1.z, a1.w};
            #pragma unroll
            for (int r = 0; r < 8; r++) {
                ull ap = pack2(ar[r]);
                fma2(acc[r][0], ap, bb.x);
                fma2(acc[r][1], ap, bb.y);
            }
        }
    };

    // ---- Phase 2: 3 QKV passes, no intermediate syncs (Xst read-only, disjoint writes) ----
    #pragma unroll 1
    for (int p = 0; p < 3; p++) {
        gemm_pass(p << 7);
        // epilogue: remap interleaved-head channels to Q/K/V
        int j  = (p << 7) + (ct << 2);
        int hh = j / 96;
        int r  = j - hh * 96;
        int seg = r >> 5;
        int col = (hh << 5) + (r & 31);
        float* dst = (seg == 0) ? Qs : (seg == 1) ? Ks : Vs;
        float sc   = (seg == 0) ? SC_Q : 1.0f;
        float4 b4 = *(const float4*)(qkv_b + j);
        #pragma unroll
        for (int r8 = 0; r8 < 8; r8++) {
            int s = (rt << 3) + r8;
            float2 p0 = unpack2(acc[r8][0]);
            float2 p1 = unpack2(acc[r8][1]);
            float4 o;
            o.x = (p0.x + b4.x) * sc;
            o.y = (p0.y + b4.y) * sc;
            o.z = (p1.x + b4.z) * sc;
            o.w = (p1.y + b4.w) * sc;
            *(float4*)(dst + s * PQ + col) = o;
        }
    }
    __syncthreads();

    // ---- Phase 3: attention. thread = (head h, query q). exact softmax. ----
    {
        const int h = tid >> 6;
        const int q = tid & 63;
        ulonglong2 qp[8];
        const ulonglong2* qr = (const ulonglong2*)(Qs + q * PQ + (h << 5));
        #pragma unroll
        for (int d = 0; d < 8; d++) qp[d] = qr[d];

        float lg[64];
        const int qi = q >> 3, qj = q & 7;
        #pragma unroll
        for (int t = 0; t < 64; t++) {
            const ulonglong2* kr = (const ulonglong2*)(Ks + t * PQ + (h << 5));
            ull a0 = 0ULL, a1 = 0ULL, a2 = 0ULL, a3 = 0ULL;
            #pragma unroll
            for (int d = 0; d < 8; d += 2) {
                ulonglong2 k0 = kr[d];
                ulonglong2 k1 = kr[d + 1];
                fma2(a0, qp[d].x, k0.x);
                fma2(a1, qp[d].y, k0.y);
                fma2(a2, qp[d + 1].x, k1.x);
                fma2(a3, qp[d + 1].y, k1.y);
            }
            float2 s0 = unpack2(a0), s1 = unpack2(a1), s2 = unpack2(a2), s3 = unpack2(a3);
            int ridx = (qi - (t >> 3) + 7) * 15 + (qj - (t & 7) + 7);
            lg[t] = ((s0.x + s0.y) + (s1.x + s1.y)) + ((s2.x + s2.y) + (s3.x + s3.y))
                    + Bt[ridx * 4 + h];
        }
        float m = lg[0];
        #pragma unroll
        for (int t = 1; t < 64; t++) m = fmaxf(m, lg[t]);
        float l = 0.f;
        #pragma unroll
        for (int t = 0; t < 64; t++) { float e = __expf(lg[t] - m); lg[t] = e; l += e; }
        float inv = __fdividef(1.0f, l);

        ull op[16];
        #pragma unroll
        for (int d = 0; d < 16; d++) op[d] = 0ULL;
        #pragma unroll
        for (int t = 0; t < 64; t++) {
            ull pp = pack2(lg[t]);
            const ulonglong2* vr = (const ulonglong2*)(Vs + t * PQ + (h << 5));
            #pragma unroll
            for (int d = 0; d < 8; d++) {
                fma2(op[2 * d],     pp, vr[d].x);
                fma2(op[2 * d + 1], pp, vr[d].y);
            }
        }
        // write attention output transposed (k-major) into Xst for proj GEMM
        #pragma unroll
        for (int d = 0; d < 16; d++) {
            float2 o2 = unpack2(op[d]);
            int c = (h << 5) + 2 * d;
            Xst[c * PX + q]       = o2.x * inv;
            Xst[(c + 1) * PX + q] = o2.y * inv;
        }
    }
    __syncthreads();

    // ---- Phase 4: proj GEMM (B = Wt cols 384..511) -> Y into Qs ----
    {
        gemm_pass(384);
        int j = ct << 2;
        float4 b4 = *(const float4*)(proj_b + j);
        #pragma unroll
        for (int r8 = 0; r8 < 8; r8++) {
            int s = (rt << 3) + r8;
            float2 p0 = unpack2(acc[r8][0]);
            float2 p1 = unpack2(acc[r8][1]);
            float4 o;
            o.x = p0.x + b4.x;
            o.y = p0.y + b4.y;
            o.z = p1.x + b4.z;
            o.w = p1.y + b4.w;
            *(float4*)(Qs + s * PQ + j) = o;
        }
    }
    __syncthreads();

    // ---- Phase 5: coalesced reverse-roll scatter ----
    float* ob = out + base;
    #pragma unroll
    for (int i = tid; i < 8192; i += 256) {
        int c = i >> 6, s = i & 63;
        int sh = ((hn << 3) + (s >> 3) - 4) & 63;
        int sw = ((wn << 3) + (s & 7) - 4) & 63;
        ob[c * 102400 + sh * 64 + sw] = Qs[s * PQ + c];
    }
}

extern "C" void kernel_launch(void* const* d_in, const int* in_sizes, int n_in,
                              void* d_out, int out_size) {
    (void)in_sizes; (void)n_in; (void)out_size;
    prep_w_kernel<<<256, 256>>>((const float*)d_in[1], (const float*)d_in[3]);
    size_t smem = SMEM_FLOATS * sizeof(float);
    cudaFuncSetAttribute(wattn_kernel, cudaFuncAttributeMaxDynamicSharedMemorySize, (int)smem);
    wattn_kernel<<<3200, 256, smem>>>(
        (const float*)d_in[0], (const float*)d_in[2], (const float*)d_in[4],
        (const float*)d_in[5], (float*)d_out);
}

// round 6
// speedup vs baseline: 1.3202x; 1.0551x over previous
#include <cuda_runtime.h>
#include <cstdint>

typedef unsigned long long ull;

#define PX 68    // Xst pitch (floats)
#define PQ 132   // Q/K/V/Y pitch
#define SC_Q 0.17677669529663687f  // 32^-0.5

// packed fp32x2 FMA (sm_10x): doubles fp32 throughput vs FFMA
__device__ __forceinline__ void fma2(ull &d, ull a, ull b) {
    asm volatile("fma.rn.f32x2 %0, %1, %2, %0;" : "+l"(d) : "l"(a), "l"(b));
}
__device__ __forceinline__ ull pack2(float x) {
    ull d; unsigned u = __float_as_uint(x);
    asm volatile("mov.b64 %0, {%1, %1};" : "=l"(d) : "r"(u));
    return d;
}
__device__ __forceinline__ float2 unpack2(ull d) {
    float2 r;
    asm volatile("mov.b64 {%0, %1}, %2;" : "=f"(r.x), "=f"(r.y) : "l"(d));
    return r;
}

// Pre-transposed weights: Wt[k][j], j in [0,384) = qkv row j, j in [384,512) = proj row j-384
__device__ float Wt_g[128 * 512];

__global__ void __launch_bounds__(256)
prep_w_kernel(const float* __restrict__ qkv_w, const float* __restrict__ proj_w) {
    int i = blockIdx.x * 256 + threadIdx.x;   // 65536 total
    int k = i >> 9, j = i & 511;
    Wt_g[i] = (j < 384) ? qkv_w[j * 128 + k] : proj_w[(j - 384) * 128 + k];
}

// smem (floats): Xst[128*PX] | Qs[64*PQ] | Ks | Vs | Bt[900]   (~140 KB)
#define SMEM_FLOATS (128*PX + 3*64*PQ + 900)

__global__ void __launch_bounds__(256, 1)
wattn_kernel(const float* __restrict__ x, const float* __restrict__ qkv_b,
             const float* __restrict__ proj_b, const float* __restrict__ rpb,
             float* __restrict__ out)
{
    extern __shared__ float sm[];
    float* Xst = sm;                  // [128][PX] input (k-major), later attn out (k-major)
    float* Qs  = Xst + 128 * PX;      // [64][PQ] Q (prescaled), later final Y
    float* Ks  = Qs + 64 * PQ;        // K; later proj partial-sum scratch
    float* Vs  = Ks + 64 * PQ;
    float* Bt  = Vs + 64 * PQ;        // rpb [225*4]

    const int tid = threadIdx.x;
    int wid = blockIdx.x;
    const int wn = wid & 7;  wid >>= 3;
    const int hn = wid & 7;  wid >>= 3;
    const int v  = wid % 5;  wid /= 5;
    const int u  = wid % 5;
    const int b  = wid / 5;

    // base for (b, c=0, u, v): layout (B,C,U,V,H,W), C-stride = 25*4096 = 102400
    const int base = (((b << 7) * 5 + u) * 5 + v) * 4096;
    const float* xb = x + base;

    // ---- Phase 1: roll + window gather into Xst[c][s]; rpb -> Bt ----
    #pragma unroll
    for (int i = tid; i < 8192; i += 256) {
        int c = i >> 6, s = i & 63;
        int sh = ((hn << 3) + (s >> 3) - 4) & 63;
        int sw = ((wn << 3) + (s & 7) - 4) & 63;
        Xst[c * PX + s] = __ldg(xb + c * 102400 + sh * 64 + sw);
    }
    for (int i = tid; i < 900; i += 256) Bt[i] = rpb[i];
    __syncthreads();

    // ---- Phase 2: FUSED QKV GEMM. 256 threads, 8 rows x (3 x 4 cols). ----
    // Amortizes A-loads+pack over 48 fma2 per k (was 16).
    {
        const int rt = tid >> 5;   // row block: rows rt*8..+7 (warp-uniform -> broadcast)
        const int ct = tid & 31;   // col quad within each 128-col section

        ull acc[3][8][2];
        #pragma unroll
        for (int p = 0; p < 3; p++)
            #pragma unroll
            for (int r = 0; r < 8; r++) { acc[p][r][0] = 0ULL; acc[p][r][1] = 0ULL; }

        const float* Bp = Wt_g + (ct << 2);
        #pragma unroll 4
        for (int k = 0; k < 128; k++) {
            const float* Ar = Xst + k * PX + (rt << 3);
            float4 a0 = *(const float4*)(Ar);
            float4 a1 = *(const float4*)(Ar + 4);
            const float* Bk = Bp + (k << 9);
            ulonglong2 b0 = *(const ulonglong2*)(Bk);
            ulonglong2 b1 = *(const ulonglong2*)(Bk + 128);
            ulonglong2 b2 = *(const ulonglong2*)(Bk + 256);
            float ar[8] = {a0.x, a0.y, a0.z, a0.w, a1.x, a1.y, a1.z, a1.w};
            #pragma unroll
            for (int r = 0; r < 8; r++) {
                ull ap = pack2(ar[r]);
                fma2(acc[0][r][0], ap, b0.x);
                fma2(acc[0][r][1], ap, b0.y);
                fma2(acc[1][r][0], ap, b1.x);
                fma2(acc[1][r][1], ap, b1.y);
                fma2(acc[2][r][0], ap, b2.x);
                fma2(acc[2][r][1], ap, b2.y);
            }
        }

        // epilogue x3: remap interleaved-head channels to Q/K/V
        #pragma unroll
        for (int p = 0; p < 3; p++) {
            int j  = (p << 7) + (ct << 2);
            int hh = j / 96;
            int r  = j - hh * 96;
            int seg = r >> 5;
            int col = (hh << 5) + (r & 31);
            float* dst = (seg == 0) ? Qs : (seg == 1) ? Ks : Vs;
            float sc   = (seg == 0) ? SC_Q : 1.0f;
            float4 b4 = *(const float4*)(qkv_b + j);
            #pragma unroll
            for (int r8 = 0; r8 < 8; r8++) {
                int s = (rt << 3) + r8;
                float2 p0 = unpack2(acc[p][r8][0]);
                float2 p1 = unpack2(acc[p][r8][1]);
                float4 o;
                o.x = (p0.x + b4.x) * sc;
                o.y = (p0.y + b4.y) * sc;
                o.z = (p1.x + b4.z) * sc;
                o.w = (p1.y + b4.w) * sc;
                *(float4*)(dst + s * PQ + col) = o;
            }
        }
    }
    __syncthreads();

    // ---- Phase 3: attention. thread = (head h, query q). exact softmax. ----
    {
        const int h = tid >> 6;
        const int q = tid & 63;
        ulonglong2 qp[8];
        const ulonglong2* qr = (const ulonglong2*)(Qs + q * PQ + (h << 5));
        #pragma unroll
        for (int d = 0; d < 8; d++) qp[d] = qr[d];

        float lg[64];
        const int qi = q >> 3, qj = q & 7;
        #pragma unroll
        for (int t = 0; t < 64; t++) {
            const ulonglong2* kr = (const ulonglong2*)(Ks + t * PQ + (h << 5));
            ull a0 = 0ULL, a1 = 0ULL, a2 = 0ULL, a3 = 0ULL;
            #pragma unroll
            for (int d = 0; d < 8; d += 2) {
                ulonglong2 k0 = kr[d];
                ulonglong2 k1 = kr[d + 1];
                fma2(a0, qp[d].x, k0.x);
                fma2(a1, qp[d].y, k0.y);
                fma2(a2, qp[d + 1].x, k1.x);
                fma2(a3, qp[d + 1].y, k1.y);
            }
            float2 s0 = unpack2(a0), s1 = unpack2(a1), s2 = unpack2(a2), s3 = unpack2(a3);
            int ridx = (qi - (t >> 3) + 7) * 15 + (qj - (t & 7) + 7);
            lg[t] = ((s0.x + s0.y) + (s1.x + s1.y)) + ((s2.x + s2.y) + (s3.x + s3.y))
                    + Bt[ridx * 4 + h];
        }
        float m = lg[0];
        #pragma unroll
        for (int t = 1; t < 64; t++) m = fmaxf(m, lg[t]);
        float l = 0.f;
        #pragma unroll
        for (int t = 0; t < 64; t++) { float e = __expf(lg[t] - m); lg[t] = e; l += e; }
        float inv = __fdividef(1.0f, l);

        ull op[16];
        #pragma unroll
        for (int d = 0; d < 16; d++) op[d] = 0ULL;
        #pragma unroll
        for (int t = 0; t < 64; t++) {
            ull pp = pack2(lg[t]);
            const ulonglong2* vr = (const ulonglong2*)(Vs + t * PQ + (h << 5));
            #pragma unroll
            for (int d = 0; d < 8; d++) {
                fma2(op[2 * d],     pp, vr[d].x);
                fma2(op[2 * d + 1], pp, vr[d].y);
            }
        }
        // write attention output transposed (k-major) into Xst for proj GEMM
        #pragma unroll
        for (int d = 0; d < 16; d++) {
            float2 o2 = unpack2(op[d]);
            int c = (h << 5) + 2 * d;
            Xst[c * PX + q]       = o2.x * inv;
            Xst[(c + 1) * PX + q] = o2.y * inv;
        }
    }
    __syncthreads();

    // ---- Phase 4: proj GEMM, 8x8 tiles, 2-way k-split over 256 threads ----
    {
        const int g   = tid >> 7;          // k-half
        const int rt8 = (tid >> 4) & 7;    // row block (8 rows)
        const int ct8 = tid & 15;          // col block (8 cols)

        ull pacc[8][4];
        #pragma unroll
        for (int r = 0; r < 8; r++)
            #pragma unroll
            for (int c = 0; c < 4; c++) pacc[r][c] = 0ULL;

        const float* Bq = Wt_g + 384 + (ct8 << 3);
        #pragma unroll 4
        for (int kk = 0; kk < 64; kk++) {
            int k = (g << 6) + kk;
            const float* Ar = Xst + k * PX + (rt8 << 3);
            float4 a0 = *(const float4*)(Ar);
            float4 a1 = *(const float4*)(Ar + 4);
            const float* Bk = Bq + (k << 9);
            ulonglong2 b0 = *(const ulonglong2*)(Bk);
            ulonglong2 b1 = *(const ulonglong2*)(Bk + 4);
            float ar[8] = {a0.x, a0.y, a0.z, a0.w, a1.x, a1.y, a1.z, a1.w};
            #pragma unroll
            for (int r = 0; r < 8; r++) {
                ull ap = pack2(ar[r]);
                fma2(pacc[r][0], ap, b0.x);
                fma2(pacc[r][1], ap, b0.y);
                fma2(pacc[r][2], ap, b1.x);
                fma2(pacc[r][3], ap, b1.y);
            }
        }

        // k-half 1 stores partials into Ks scratch (free after attention)
        if (g == 1) {
            #pragma unroll
            for (int r8 = 0; r8 < 8; r8++) {
                int s = (rt8 << 3) + r8;
                float2 p0 = unpack2(pacc[r8][0]);
                float2 p1 = unpack2(pacc[r8][1]);
                float2 p2 = unpack2(pacc[r8][2]);
                float2 p3 = unpack2(pacc[r8][3]);
                float* dst = Ks + s * PQ + (ct8 << 3);
                *(float4*)(dst)     = make_float4(p0.x, p0.y, p1.x, p1.y);
                *(float4*)(dst + 4) = make_float4(p2.x, p2.y, p3.x, p3.y);
            }
        }
        __syncthreads();
        if (g == 0) {
            int j = ct8 << 3;
            float4 b40 = *(const float4*)(proj_b + j);
            float4 b41 = *(const float4*)(proj_b + j + 4);
            #pragma unroll
            for (int r8 = 0; r8 < 8; r8++) {
                int s = (rt8 << 3) + r8;
                const float* src = Ks + s * PQ + j;
                float4 q0 = *(const float4*)(src);
                float4 q1 = *(const float4*)(src + 4);
                float2 p0 = unpack2(pacc[r8][0]);
                float2 p1 = unpack2(pacc[r8][1]);
                float2 p2 = unpack2(pacc[r8][2]);
                float2 p3 = unpack2(pacc[r8][3]);
                float4 o0, o1;
                o0.x = p0.x + q0.x + b40.x;
                o0.y = p0.y + q0.y + b40.y;
                o0.z = p1.x + q0.z + b40.z;
                o0.w = p1.y + q0.w + b40.w;
                o1.x = p2.x + q1.x + b41.x;
                o1.y = p2.y + q1.y + b41.y;
                o1.z = p3.x + q1.z + b41.z;
                o1.w = p3.y + q1.w + b41.w;
                float* dst = Qs + s * PQ + j;
                *(float4*)(dst)     = o0;
                *(float4*)(dst + 4) = o1;
            }
        }
    }
    __syncthreads();

    // ---- Phase 5: coalesced reverse-roll scatter ----
    float* ob = out + base;
    #pragma unroll
    for (int i = tid; i < 8192; i += 256) {
        int c = i >> 6, s = i & 63;
        int sh = ((hn << 3) + (s >> 3) - 4) & 63;
        int sw = ((wn << 3) + (s & 7) - 4) & 63;
        ob[c * 102400 + sh * 64 + sw] = Qs[s * PQ + c];
    }
}

extern "C" void kernel_launch(void* const* d_in, const int* in_sizes, int n_in,
                              void* d_out, int out_size) {
    (void)in_sizes; (void)n_in; (void)out_size;
    prep_w_kernel<<<256, 256>>>((const float*)d_in[1], (const float*)d_in[3]);
    size_t smem = SMEM_FLOATS * sizeof(float);
    cudaFuncSetAttribute(wattn_kernel, cudaFuncAttributeMaxDynamicSharedMemorySize, (int)smem);
    wattn_kernel<<<3200, 256, smem>>>(
        (const float*)d_in[0], (const float*)d_in[2], (const float*)d_in[4],
        (const float*)d_in[5], (float*)d_out);
}